// round 5
// baseline (speedup 1.0000x reference)
#include <cuda_runtime.h>

// Problem constants
#define SQ    64          // sequence length S
#define DM    256         // d_model
#define DKV   128         // kv width
#define NH    8           // heads
#define HD    32          // head dim
#define CC    128         // C
#define DPAD  260         // padded row stride for [64,256] smem tiles
#define KVPAD 132         // padded row stride for [64,128] smem tiles
#define RS    (CC*DM)     // gmem stride between s-steps = 32768
#define BSCD  (8*SQ*CC*DM)

struct Params {
    const float* in[28];
    float* out;
};

// ---------------------------------------------------------------- tile load
__device__ __forceinline__ void load_tile(const float* __restrict__ src, int base,
                                          float* __restrict__ dst, int tid)
{
#pragma unroll
    for (int u = 0; u < 16; u++) {
        int i   = tid + u * 256;          // 4096 float4 total
        int row = i >> 6;
        int c4  = i & 63;
        float4 v = *(const float4*)(src + base + row * RS + c4 * 4);
        *(float4*)(dst + row * DPAD + c4 * 4) = v;
    }
}

// ---------------------------------------------------------------- layernorm (in place)
__device__ __forceinline__ void layernorm_tile(float* __restrict__ A,
                                               const float* __restrict__ Gg,
                                               const float* __restrict__ Bg, int tid)
{
    int w = tid >> 5, lane = tid & 31;
#pragma unroll
    for (int j = 0; j < 8; j++) {
        int r = w * 8 + j;
        float* row = A + r * DPAD;
        float v[8];
        float s1 = 0.f, s2 = 0.f;
#pragma unroll
        for (int k2 = 0; k2 < 8; k2++) {
            float x = row[lane + 32 * k2];
            v[k2] = x; s1 += x; s2 += x * x;
        }
#pragma unroll
        for (int o = 16; o > 0; o >>= 1) {
            s1 += __shfl_xor_sync(0xffffffffu, s1, o);
            s2 += __shfl_xor_sync(0xffffffffu, s2, o);
        }
        float mu   = s1 * (1.f / 256.f);
        float var  = s2 * (1.f / 256.f) - mu * mu;
        float rstd = rsqrtf(var + 1e-5f);
#pragma unroll
        for (int k2 = 0; k2 < 8; k2++) {
            int col = lane + 32 * k2;
            row[col] = (v[k2] - mu) * rstd * Gg[col] + Bg[col];
        }
    }
}

// ---------------------------------------------------------------- GEMM: C[64][N] = A[64][256] @ W[256][N] + bias
// 256 threads as 16x16; each thread: 4 rows x (N/64 groups of 4 contiguous cols).
// Weight chunks of 8 K-rows double-buffered in smem via register prefetch.
template <int N>
__device__ __forceinline__ void gemm_tile(const float* __restrict__ Asm,
                                          const float* __restrict__ Wg,
                                          const float* __restrict__ bias,
                                          float* __restrict__ Csm, int cpad,
                                          float* __restrict__ Ws, int tid)
{
    constexpr int KB   = 8;
    constexpr int NJ   = N / 64;
    constexpr int LDPT = (KB * N) / (4 * 256);   // float4 per thread per chunk
    const int tx = tid & 15, ty = tid >> 4;

    float acc[4][NJ][4];
#pragma unroll
    for (int j = 0; j < NJ; j++) {
        float4 bv = *(const float4*)(bias + tx * 4 + 64 * j);
#pragma unroll
        for (int r = 0; r < 4; r++) {
            acc[r][j][0] = bv.x; acc[r][j][1] = bv.y;
            acc[r][j][2] = bv.z; acc[r][j][3] = bv.w;
        }
    }

    // stage chunk 0
    float4 pre[LDPT];
#pragma unroll
    for (int u = 0; u < LDPT; u++) {
        int i = tid + u * 256;
        int kk = i / (N / 4), c4 = i % (N / 4);
        pre[u] = *(const float4*)(Wg + kk * N + c4 * 4);
    }
    __syncthreads();   // guard Ws against previous user
#pragma unroll
    for (int u = 0; u < LDPT; u++)
        *(float4*)(Ws + (tid + u * 256) * 4) = pre[u];
    __syncthreads();

    const int NCH = 256 / KB;   // 32 chunks
    for (int t = 0; t < NCH; t++) {
        const float* buf = Ws + (t & 1) * (KB * N);
        float4 nxt[LDPT];
        if (t + 1 < NCH) {
            int k0 = (t + 1) * KB;
#pragma unroll
            for (int u = 0; u < LDPT; u++) {
                int i = tid + u * 256;
                int kk = i / (N / 4), c4 = i % (N / 4);
                nxt[u] = *(const float4*)(Wg + (k0 + kk) * N + c4 * 4);
            }
        }
        const float* Ab = Asm + (ty * 4) * DPAD + t * KB;
#pragma unroll
        for (int kk = 0; kk < KB; kk++) {
            float a0 = Ab[0 * DPAD + kk];
            float a1 = Ab[1 * DPAD + kk];
            float a2 = Ab[2 * DPAD + kk];
            float a3 = Ab[3 * DPAD + kk];
#pragma unroll
            for (int j = 0; j < NJ; j++) {
                float4 w = *(const float4*)(buf + kk * N + tx * 4 + 64 * j);
                acc[0][j][0] += a0 * w.x; acc[0][j][1] += a0 * w.y;
                acc[0][j][2] += a0 * w.z; acc[0][j][3] += a0 * w.w;
                acc[1][j][0] += a1 * w.x; acc[1][j][1] += a1 * w.y;
                acc[1][j][2] += a1 * w.z; acc[1][j][3] += a1 * w.w;
                acc[2][j][0] += a2 * w.x; acc[2][j][1] += a2 * w.y;
                acc[2][j][2] += a2 * w.z; acc[2][j][3] += a2 * w.w;
                acc[3][j][0] += a3 * w.x; acc[3][j][1] += a3 * w.y;
                acc[3][j][2] += a3 * w.z; acc[3][j][3] += a3 * w.w;
            }
        }
        if (t + 1 < NCH) {
            __syncthreads();   // everyone done reading buf[(t+1)&1] from iter t-1
            float* nb = Ws + ((t + 1) & 1) * (KB * N);
#pragma unroll
            for (int u = 0; u < LDPT; u++)
                *(float4*)(nb + (tid + u * 256) * 4) = nxt[u];
            __syncthreads();
        }
    }

#pragma unroll
    for (int r = 0; r < 4; r++)
#pragma unroll
        for (int j = 0; j < NJ; j++) {
            float4 o = make_float4(acc[r][j][0], acc[r][j][1], acc[r][j][2], acc[r][j][3]);
            *(float4*)(Csm + (ty * 4 + r) * cpad + tx * 4 + 64 * j) = o;
        }
}

// ---------------------------------------------------------------- attention: warp = head, online softmax, 2 rows/lane
__device__ __forceinline__ void attention(const float* __restrict__ Qb,
                                          const float* __restrict__ Kb,
                                          const float* __restrict__ Vb,
                                          float* __restrict__ Osm, int tid)
{
    const int h = tid >> 5, lane = tid & 31;
    const int qoff = h * HD;
    const int koff = (h >> 1) * HD;     // GQA: head h uses kv-head h/2
    const float scale = 0.17677669529663689f;  // 1/sqrt(32)
    const int r0 = lane, r1 = lane + 32;

    float q0[HD], q1[HD];
#pragma unroll
    for (int i = 0; i < HD; i++) {
        q0[i] = Qb[r0 * DPAD + qoff + i] * scale;
        q1[i] = Qb[r1 * DPAD + qoff + i] * scale;
    }
    float m0 = -1e30f, m1 = -1e30f, s0 = 0.f, s1 = 0.f;
    float o0[HD], o1[HD];
#pragma unroll
    for (int i = 0; i < HD; i++) { o0[i] = 0.f; o1[i] = 0.f; }

    for (int key = 0; key < SQ; key++) {
        float d0 = 0.f, d1 = 0.f;
        const float* kr = Kb + key * KVPAD + koff;
#pragma unroll
        for (int i = 0; i < HD; i++) {
            float kv = kr[i];           // broadcast across lanes
            d0 += q0[i] * kv;
            d1 += q1[i] * kv;
        }
        float nm0 = fmaxf(m0, d0), nm1 = fmaxf(m1, d1);
        float a0 = __expf(m0 - nm0), a1 = __expf(m1 - nm1);
        float w0 = __expf(d0 - nm0), w1 = __expf(d1 - nm1);
        s0 = s0 * a0 + w0; s1 = s1 * a1 + w1;
        m0 = nm0; m1 = nm1;
        const float* vr = Vb + key * KVPAD + koff;
#pragma unroll
        for (int i = 0; i < HD; i++) {
            float vv = vr[i];           // broadcast across lanes
            o0[i] = o0[i] * a0 + w0 * vv;
            o1[i] = o1[i] * a1 + w1 * vv;
        }
    }
    float inv0 = 1.f / s0, inv1 = 1.f / s1;
#pragma unroll
    for (int i = 0; i < HD; i++) {
        Osm[r0 * DPAD + qoff + i] = o0[i] * inv0;
        Osm[r1 * DPAD + qoff + i] = o1[i] * inv1;
    }
}

// ---------------------------------------------------------------- main fused kernel
// grid = (1024 sequences, 2 branches), block = 256 threads
__global__ void __launch_bounds__(256, 1)
cfb_kernel(Params P)
{
    extern __shared__ float sm[];
    float* A  = sm;            // [64][260] : ln_q -> ln_kv -> attn_out
    float* Qb = sm + 16640;    // [64][260] : q -> delta
    float* Kb = sm + 33280;    // [64][132]
    float* Vb = sm + 41728;    // [64][132]
    float* Ws = sm + 50176;    // 2 x 8 x 256 double-buffered weight chunks
    float* Gg = sm + 54272;    // [256] gamma
    float* Bg = sm + 54528;    // [256] beta
    // total floats = 54784 -> 219136 bytes

    const int tid = threadIdx.x;
    const int n  = blockIdx.x;
    const int br = blockIdx.y;
    const int b = n >> 7, c = n & 127;
    const int base = b * (SQ * CC * DM) + c * DM;

    // operand routing per branch: br=0 (s2t): q from spec, kv from spat
    const float* xq     = P.in[br ? 1 : 0];
    const float* xkv    = P.in[br ? 0 : 1];
    const float* lnq_g  = P.in[br ? 6 : 2];
    const float* lnq_b  = P.in[br ? 7 : 3];
    const float* lnkv_g = P.in[br ? 4 : 8];
    const float* lnkv_b = P.in[br ? 5 : 9];
    const int wb = 10 + br * 8;
    const float* Wq = P.in[wb + 0]; const float* bq = P.in[wb + 1];
    const float* Wk = P.in[wb + 2]; const float* bk = P.in[wb + 3];
    const float* Wv = P.in[wb + 4]; const float* bv = P.in[wb + 5];
    const float* Wo = P.in[wb + 6]; const float* bo = P.in[wb + 7];
    const float* gate = P.in[26 + br];
    float* outp = P.out + (size_t)br * BSCD;

    // --- Q path ---
    load_tile(xq, base, A, tid);
    Gg[tid] = lnq_g[tid];
    Bg[tid] = lnq_b[tid];
    __syncthreads();
    layernorm_tile(A, Gg, Bg, tid);
    __syncthreads();
    gemm_tile<256>(A, Wq, bq, Qb, DPAD, Ws, tid);
    __syncthreads();

    // --- KV path (reuse A) ---
    load_tile(xkv, base, A, tid);
    Gg[tid] = lnkv_g[tid];
    Bg[tid] = lnkv_b[tid];
    __syncthreads();
    layernorm_tile(A, Gg, Bg, tid);
    __syncthreads();
    gemm_tile<128>(A, Wk, bk, Kb, KVPAD, Ws, tid);
    __syncthreads();
    gemm_tile<128>(A, Wv, bv, Vb, KVPAD, Ws, tid);
    __syncthreads();

    // --- attention (writes into A) ---
    attention(Qb, Kb, Vb, A, tid);
    __syncthreads();

    // --- output projection (delta into Qb) ---
    gemm_tile<256>(A, Wo, bo, Qb, DPAD, Ws, tid);
    __syncthreads();

    // --- gated residual epilogue ---
    float gv = 1.f / (1.f + __expf(-gate[0]));
#pragma unroll
    for (int u = 0; u < 16; u++) {
        int i   = tid + u * 256;
        int row = i >> 6;
        int c4  = i & 63;
        float4 x = *(const float4*)(xq + base + row * RS + c4 * 4);
        float4 d = *(const float4*)(Qb + row * DPAD + c4 * 4);
        float4 o = make_float4(x.x + gv * d.x, x.y + gv * d.y,
                               x.z + gv * d.z, x.w + gv * d.w);
        *(float4*)(outp + base + row * RS + c4 * 4) = o;
    }
}

extern "C" void kernel_launch(void* const* d_in, const int* in_sizes, int n_in,
                              void* d_out, int out_size)
{
    Params P;
    for (int i = 0; i < 28; i++) P.in[i] = (const float*)d_in[i];
    P.out = (float*)d_out;

    const int smem_bytes = 219136;
    cudaFuncSetAttribute(cfb_kernel, cudaFuncAttributeMaxDynamicSharedMemorySize, smem_bytes);

    dim3 grid(1024, 2), block(256);
    cfb_kernel<<<grid, block, smem_bytes>>>(P);
}

// round 7
// speedup vs baseline: 1.0687x; 1.0687x over previous
#include <cuda_runtime.h>

// Problem constants
#define SQ    64          // sequence length S
#define DM    256         // d_model
#define DKV   128         // kv width
#define NH    8           // heads
#define HD    32          // head dim
#define CC    128         // C
#define DPAD  260         // padded row stride for [64,256] smem tiles
#define KVPAD 132         // padded row stride for [64,128] smem tiles
#define RS    (CC*DM)     // gmem stride between s-steps = 32768
#define BSCD  (8*SQ*CC*DM)

typedef unsigned long long ull;

struct Params {
    const float* in[28];
    float* out;
};

// ---------------------------------------------------------------- f32x2 helpers
__device__ __forceinline__ ull pack2(float lo, float hi) {
    ull r; asm("mov.b64 %0, {%1, %2};" : "=l"(r) : "f"(lo), "f"(hi)); return r;
}
__device__ __forceinline__ ull fma2(ull a, ull b, ull c) {
    ull d; asm("fma.rn.f32x2 %0, %1, %2, %3;" : "=l"(d) : "l"(a), "l"(b), "l"(c)); return d;
}
__device__ __forceinline__ ull mul2(ull a, ull b) {
    ull d; asm("mul.rn.f32x2 %0, %1, %2;" : "=l"(d) : "l"(a), "l"(b)); return d;
}
__device__ __forceinline__ float2 unpk2(ull v) {
    float2 f; asm("mov.b64 {%0, %1}, %2;" : "=f"(f.x), "=f"(f.y) : "l"(v)); return f;
}

// ---------------------------------------------------------------- tile load
__device__ __forceinline__ void load_tile(const float* __restrict__ src, int base,
                                          float* __restrict__ dst, int tid)
{
#pragma unroll
    for (int u = 0; u < 16; u++) {
        int i   = tid + u * 256;          // 4096 float4 total
        int row = i >> 6;
        int c4  = i & 63;
        float4 v = *(const float4*)(src + base + row * RS + c4 * 4);
        *(float4*)(dst + row * DPAD + c4 * 4) = v;
    }
}

// ---------------------------------------------------------------- layernorm (in place)
__device__ __forceinline__ void layernorm_tile(float* __restrict__ A,
                                               const float* __restrict__ Gg,
                                               const float* __restrict__ Bg, int tid)
{
    int w = tid >> 5, lane = tid & 31;
#pragma unroll
    for (int j = 0; j < 8; j++) {
        int r = w * 8 + j;
        float* row = A + r * DPAD;
        float v[8];
        float s1 = 0.f, s2 = 0.f;
#pragma unroll
        for (int k2 = 0; k2 < 8; k2++) {
            float x = row[lane + 32 * k2];
            v[k2] = x; s1 += x; s2 += x * x;
        }
#pragma unroll
        for (int o = 16; o > 0; o >>= 1) {
            s1 += __shfl_xor_sync(0xffffffffu, s1, o);
            s2 += __shfl_xor_sync(0xffffffffu, s2, o);
        }
        float mu   = s1 * (1.f / 256.f);
        float var  = s2 * (1.f / 256.f) - mu * mu;
        float rstd = rsqrtf(var + 1e-5f);
#pragma unroll
        for (int k2 = 0; k2 < 8; k2++) {
            int col = lane + 32 * k2;
            row[col] = (v[k2] - mu) * rstd * Gg[col] + Bg[col];
        }
    }
}

// ---------------------------------------------------------------- GEMM: C[64][N] = A[64][256] @ W[256][N] + bias
// 256 threads as 16x16; thread owns 4 rows x (N/64 groups of 4 cols, packed as 2x f32x2).
// Weight chunks of 8 K-rows TRIPLE-buffered in smem (1 sync per chunk).
template <int N>
__device__ __forceinline__ void gemm_tile(const float* __restrict__ Asm,
                                          const float* __restrict__ Wg,
                                          const float* __restrict__ bias,
                                          float* __restrict__ Csm, int cpad,
                                          float* __restrict__ Ws, int tid)
{
    constexpr int KB   = 8;
    constexpr int NJ   = N / 64;
    constexpr int LDPT = (KB * N) / (4 * 256);   // float4 per thread per chunk
    const int tx = tid & 15, ty = tid >> 4;

    ull acc[4][NJ][2];
#pragma unroll
    for (int j = 0; j < NJ; j++) {
        float4 bv = *(const float4*)(bias + tx * 4 + 64 * j);
        ull p0 = pack2(bv.x, bv.y), p1 = pack2(bv.z, bv.w);
#pragma unroll
        for (int r = 0; r < 4; r++) { acc[r][j][0] = p0; acc[r][j][1] = p1; }
    }

    // stage chunk 0 (caller already synced after previous Ws user)
    {
        float4 pre[LDPT];
#pragma unroll
        for (int u = 0; u < LDPT; u++) {
            int i = tid + u * 256;
            int kk = i / (N / 4), c4 = i % (N / 4);
            pre[u] = *(const float4*)(Wg + kk * N + c4 * 4);
        }
#pragma unroll
        for (int u = 0; u < LDPT; u++)
            *(float4*)(Ws + (tid + u * 256) * 4) = pre[u];
        __syncthreads();
    }

    const int NCH = 256 / KB;   // 32 chunks
    for (int t = 0; t < NCH; t++) {
        const float* buf = Ws + (t % 3) * (KB * N);
        float4 nxt[LDPT];
        if (t + 1 < NCH) {
            int k0 = (t + 1) * KB;
#pragma unroll
            for (int u = 0; u < LDPT; u++) {
                int i = tid + u * 256;
                int kk = i / (N / 4), c4 = i % (N / 4);
                nxt[u] = *(const float4*)(Wg + (k0 + kk) * N + c4 * 4);
            }
        }
        // vector-load the 8 A-values for each of this thread's 4 rows
        const float* Ab = Asm + (ty * 4) * DPAD + t * KB;
        float a[4][8];
#pragma unroll
        for (int r = 0; r < 4; r++) {
            float4 v0 = *(const float4*)(Ab + r * DPAD);
            float4 v1 = *(const float4*)(Ab + r * DPAD + 4);
            a[r][0] = v0.x; a[r][1] = v0.y; a[r][2] = v0.z; a[r][3] = v0.w;
            a[r][4] = v1.x; a[r][5] = v1.y; a[r][6] = v1.z; a[r][7] = v1.w;
        }
#pragma unroll
        for (int kk = 0; kk < KB; kk++) {
            ull aw0 = pack2(a[0][kk], a[0][kk]);
            ull aw1 = pack2(a[1][kk], a[1][kk]);
            ull aw2 = pack2(a[2][kk], a[2][kk]);
            ull aw3 = pack2(a[3][kk], a[3][kk]);
#pragma unroll
            for (int j = 0; j < NJ; j++) {
                ulonglong2 w = *(const ulonglong2*)(buf + kk * N + tx * 4 + 64 * j);
                acc[0][j][0] = fma2(aw0, w.x, acc[0][j][0]);
                acc[0][j][1] = fma2(aw0, w.y, acc[0][j][1]);
                acc[1][j][0] = fma2(aw1, w.x, acc[1][j][0]);
                acc[1][j][1] = fma2(aw1, w.y, acc[1][j][1]);
                acc[2][j][0] = fma2(aw2, w.x, acc[2][j][0]);
                acc[2][j][1] = fma2(aw2, w.y, acc[2][j][1]);
                acc[3][j][0] = fma2(aw3, w.x, acc[3][j][0]);
                acc[3][j][1] = fma2(aw3, w.y, acc[3][j][1]);
            }
        }
        if (t + 1 < NCH) {
            // triple buffer: last readers of buf[(t+1)%3] were iteration t-2,
            // separated by >=2 syncs -> safe to overwrite now
            float* nb = Ws + ((t + 1) % 3) * (KB * N);
#pragma unroll
            for (int u = 0; u < LDPT; u++)
                *(float4*)(nb + (tid + u * 256) * 4) = nxt[u];
            __syncthreads();
        }
    }

#pragma unroll
    for (int r = 0; r < 4; r++)
#pragma unroll
        for (int j = 0; j < NJ; j++) {
            ulonglong2 o; o.x = acc[r][j][0]; o.y = acc[r][j][1];
            *(ulonglong2*)(Csm + (ty * 4 + r) * cpad + tx * 4 + 64 * j) = o;
        }
}

// ---------------------------------------------------------------- attention: warp = head, online softmax, 2 rows/lane
__device__ __forceinline__ void attention(const float* __restrict__ Qb,
                                          const float* __restrict__ Kb,
                                          const float* __restrict__ Vb,
                                          float* __restrict__ Osm, int tid)
{
    const int h = tid >> 5, lane = tid & 31;
    const int qoff = h * HD;
    const int koff = (h >> 1) * HD;     // GQA: head h uses kv-head h/2
    const float scale = 0.17677669529663689f;  // 1/sqrt(32)
    const int r0 = lane, r1 = lane + 32;

    ull sc2 = pack2(scale, scale);
    ull q0[HD/2], q1[HD/2];
#pragma unroll
    for (int ii = 0; ii < HD/4; ii++) {
        ulonglong2 t0 = *(const ulonglong2*)(Qb + r0 * DPAD + qoff + ii * 4);
        ulonglong2 t1 = *(const ulonglong2*)(Qb + r1 * DPAD + qoff + ii * 4);
        q0[2*ii]   = mul2(t0.x, sc2); q0[2*ii+1] = mul2(t0.y, sc2);
        q1[2*ii]   = mul2(t1.x, sc2); q1[2*ii+1] = mul2(t1.y, sc2);
    }
    float m0 = -1e30f, m1 = -1e30f, s0 = 0.f, s1 = 0.f;
    ull o0[HD/2], o1[HD/2];
#pragma unroll
    for (int i = 0; i < HD/2; i++) { o0[i] = 0ULL; o1[i] = 0ULL; }

    for (int key = 0; key < SQ; key++) {
        ull d0p = 0ULL, d1p = 0ULL;
        const float* kr = Kb + key * KVPAD + koff;
#pragma unroll
        for (int ii = 0; ii < HD/4; ii++) {
            ulonglong2 kv = *(const ulonglong2*)(kr + ii * 4);   // broadcast
            d0p = fma2(q0[2*ii],   kv.x, d0p);
            d0p = fma2(q0[2*ii+1], kv.y, d0p);
            d1p = fma2(q1[2*ii],   kv.x, d1p);
            d1p = fma2(q1[2*ii+1], kv.y, d1p);
        }
        float2 f0 = unpk2(d0p), f1 = unpk2(d1p);
        float d0 = f0.x + f0.y, d1 = f1.x + f1.y;

        float nm0 = fmaxf(m0, d0), nm1 = fmaxf(m1, d1);
        float a0 = __expf(m0 - nm0), a1 = __expf(m1 - nm1);
        float w0 = __expf(d0 - nm0), w1 = __expf(d1 - nm1);
        s0 = s0 * a0 + w0; s1 = s1 * a1 + w1;
        m0 = nm0; m1 = nm1;

        ull a0p = pack2(a0, a0), a1p = pack2(a1, a1);
        ull w0p = pack2(w0, w0), w1p = pack2(w1, w1);
        const float* vr = Vb + key * KVPAD + koff;
#pragma unroll
        for (int ii = 0; ii < HD/4; ii++) {
            ulonglong2 vv = *(const ulonglong2*)(vr + ii * 4);   // broadcast
            o0[2*ii]   = fma2(o0[2*ii],   a0p, mul2(w0p, vv.x));
            o0[2*ii+1] = fma2(o0[2*ii+1], a0p, mul2(w0p, vv.y));
            o1[2*ii]   = fma2(o1[2*ii],   a1p, mul2(w1p, vv.x));
            o1[2*ii+1] = fma2(o1[2*ii+1], a1p, mul2(w1p, vv.y));
        }
    }
    ull inv0 = pack2(1.f / s0, 1.f / s0);
    ull inv1 = pack2(1.f / s1, 1.f / s1);
#pragma unroll
    for (int ii = 0; ii < HD/4; ii++) {
        ulonglong2 w0o, w1o;
        w0o.x = mul2(o0[2*ii], inv0); w0o.y = mul2(o0[2*ii+1], inv0);
        w1o.x = mul2(o1[2*ii], inv1); w1o.y = mul2(o1[2*ii+1], inv1);
        *(ulonglong2*)(Osm + r0 * DPAD + qoff + ii * 4) = w0o;
        *(ulonglong2*)(Osm + r1 * DPAD + qoff + ii * 4) = w1o;
    }
}

// ---------------------------------------------------------------- main fused kernel
// grid = (1024 sequences, 2 branches), block = 256 threads
__global__ void __launch_bounds__(256, 1)
cfb_kernel(Params P)
{
    extern __shared__ float sm[];
    float* A  = sm;            // [64][260] : ln_q -> ln_kv -> attn_out
    float* Qb = sm + 16640;    // [64][260] : q -> delta
    float* Kb = sm + 33280;    // [64][132]
    float* Vb = sm + 41728;    // [64][132]
    float* Ws = sm + 50176;    // 3 x 8 x 256 triple-buffered weight chunks
    float* Gg = sm + 56320;    // [256] gamma
    float* Bg = sm + 56576;    // [256] beta
    // total floats = 56832 -> 227328 bytes

    const int tid = threadIdx.x;
    const int n  = blockIdx.x;
    const int br = blockIdx.y;
    const int b = n >> 7, c = n & 127;
    const int base = b * (SQ * CC * DM) + c * DM;

    // operand routing per branch: br=0 (s2t): q from spec, kv from spat
    const float* xq     = P.in[br ? 1 : 0];
    const float* xkv    = P.in[br ? 0 : 1];
    const float* lnq_g  = P.in[br ? 6 : 2];
    const float* lnq_b  = P.in[br ? 7 : 3];
    const float* lnkv_g = P.in[br ? 4 : 8];
    const float* lnkv_b = P.in[br ? 5 : 9];
    const int wb = 10 + br * 8;
    const float* Wq = P.in[wb + 0]; const float* bq = P.in[wb + 1];
    const float* Wk = P.in[wb + 2]; const float* bk = P.in[wb + 3];
    const float* Wv = P.in[wb + 4]; const float* bv = P.in[wb + 5];
    const float* Wo = P.in[wb + 6]; const float* bo = P.in[wb + 7];
    const float* gate = P.in[26 + br];
    float* outp = P.out + (size_t)br * BSCD;

    // --- Q path ---
    load_tile(xq, base, A, tid);
    Gg[tid] = lnq_g[tid];
    Bg[tid] = lnq_b[tid];
    __syncthreads();
    layernorm_tile(A, Gg, Bg, tid);
    __syncthreads();
    gemm_tile<256>(A, Wq, bq, Qb, DPAD, Ws, tid);
    __syncthreads();

    // --- KV path (reuse A) ---
    load_tile(xkv, base, A, tid);
    Gg[tid] = lnkv_g[tid];
    Bg[tid] = lnkv_b[tid];
    __syncthreads();
    layernorm_tile(A, Gg, Bg, tid);
    __syncthreads();
    gemm_tile<128>(A, Wk, bk, Kb, KVPAD, Ws, tid);
    __syncthreads();
    gemm_tile<128>(A, Wv, bv, Vb, KVPAD, Ws, tid);
    __syncthreads();

    // --- attention (writes into A) ---
    attention(Qb, Kb, Vb, A, tid);
    __syncthreads();

    // --- output projection (delta into Qb) ---
    gemm_tile<256>(A, Wo, bo, Qb, DPAD, Ws, tid);
    __syncthreads();

    // --- gated residual epilogue ---
    float gv = 1.f / (1.f + __expf(-gate[0]));
#pragma unroll
    for (int u = 0; u < 16; u++) {
        int i   = tid + u * 256;
        int row = i >> 6;
        int c4  = i & 63;
        float4 x = *(const float4*)(xq + base + row * RS + c4 * 4);
        float4 d = *(const float4*)(Qb + row * DPAD + c4 * 4);
        float4 o = make_float4(x.x + gv * d.x, x.y + gv * d.y,
                               x.z + gv * d.z, x.w + gv * d.w);
        *(float4*)(outp + base + row * RS + c4 * 4) = o;
    }
}

extern "C" void kernel_launch(void* const* d_in, const int* in_sizes, int n_in,
                              void* d_out, int out_size)
{
    Params P;
    for (int i = 0; i < 28; i++) P.in[i] = (const float*)d_in[i];
    P.out = (float*)d_out;

    const int smem_bytes = 227328;
    cudaFuncSetAttribute(cfb_kernel, cudaFuncAttributeMaxDynamicSharedMemorySize, smem_bytes);

    dim3 grid(1024, 2), block(256);
    cfb_kernel<<<grid, block, smem_bytes>>>(P);
}